// round 4
// baseline (speedup 1.0000x reference)
#include <cuda_runtime.h>
#include <math.h>

#define N_NODES 25600
#define N_EDGES 204800
#define ETOT    (N_EDGES + N_NODES)   // 230400
#define IN_CH   6
#define HID     64
#define HEADS   4
#define C1      (HEADS*HID)           // 256
#define G_GRAPHS 512
#define T_STEPS  50
#define OUT_DIM  30
#define NEG_SLOPE 0.2f
#define BN_INV 0.9999950000374996f    // 1/sqrt(1+1e-5)

// ---------------- scratch ----------------
__device__ float g_wsrc[24];                  // [k][h]
__device__ float g_wdst[24];
__device__ __align__(16) float g_x8[N_NODES*8];       // padded x rows
__device__ __align__(16) float g_asrc1[N_NODES*4];
__device__ __align__(16) float g_adst1[N_NODES*4];
__device__ __align__(16) float g_xagg[N_NODES*32];    // 4 heads x [x0..x5, denom, 0]
__device__ __align__(16) float g_hproj2[N_NODES*HID];
__device__ float g_asrc2[N_NODES];
__device__ float g_adst2[N_NODES];
__device__ float g_denom2[N_NODES];
__device__ __align__(16) float g_accum2[N_NODES*HID];
__device__ __align__(16) float g_xgates[N_NODES*C1];  // (t, g, 256)

// ---------------- helpers ----------------
__device__ __forceinline__ float lrelu(float v) { return v > 0.f ? v : NEG_SLOPE*v; }
__device__ __forceinline__ float eluf(float v)  { return v > 0.f ? v : expm1f(v); }
__device__ __forceinline__ float sigf(float v)  { return 1.f/(1.f+expf(-v)); }

__device__ __forceinline__ void redAdd4(float* addr, float a, float b, float c, float d) {
    asm volatile("red.global.add.v4.f32 [%0], {%1,%2,%3,%4};"
                 :: "l"(addr), "f"(a), "f"(b), "f"(c), "f"(d) : "memory");
}
__device__ __forceinline__ void ffma2(unsigned long long& d, unsigned long long a,
                                      unsigned long long b) {
    asm("fma.rn.f32x2 %0, %1, %2, %0;" : "+l"(d) : "l"(a), "l"(b));
}
__device__ __forceinline__ unsigned long long pk(float a, float b) {
    unsigned long long r;
    asm("mov.b64 %0, {%1, %2};" : "=l"(r) : "f"(a), "f"(b));
    return r;
}
__device__ __forceinline__ float2 unpk(unsigned long long v) {
    float2 r;
    asm("mov.b64 {%0, %1}, %2;" : "=f"(r.x), "=f"(r.y) : "l"(v));
    return r;
}

// ---------------- kernels ----------------
__global__ void k_pre1(const float* __restrict__ W1, const float* __restrict__ as1,
                       const float* __restrict__ ad1) {
    int t = threadIdx.x;
    if (t < 24) {
        int k = t >> 2, h = t & 3;
        float s = 0.f;
        for (int c = 0; c < 64; c++) s += W1[k*C1 + h*64 + c] * as1[h*64 + c];
        g_wsrc[t] = s;
    } else if (t >= 32 && t < 56) {
        int i = t - 32, k = i >> 2, h = i & 3;
        float s = 0.f;
        for (int c = 0; c < 64; c++) s += W1[k*C1 + h*64 + c] * ad1[h*64 + c];
        g_wdst[i] = s;
    }
}

__global__ void k_att1(const float* __restrict__ x) {
    int n = blockIdx.x*blockDim.x + threadIdx.x;
    if (n >= N_NODES) return;
    float2 xa = *(const float2*)&x[n*6];
    float2 xb = *(const float2*)&x[n*6 + 2];
    float2 xc = *(const float2*)&x[n*6 + 4];
    float xv[6] = {xa.x, xa.y, xb.x, xb.y, xc.x, xc.y};
    float s[4] = {0,0,0,0}, d[4] = {0,0,0,0};
    #pragma unroll
    for (int k = 0; k < 6; k++) {
        #pragma unroll
        for (int h = 0; h < 4; h++) {
            s[h] += xv[k]*g_wsrc[k*4+h];
            d[h] += xv[k]*g_wdst[k*4+h];
        }
    }
    *(float4*)&g_asrc1[n*4] = make_float4(s[0],s[1],s[2],s[3]);
    *(float4*)&g_adst1[n*4] = make_float4(d[0],d[1],d[2],d[3]);
    *(float4*)&g_x8[n*8]     = make_float4(xv[0],xv[1],xv[2],xv[3]);
    *(float4*)&g_x8[n*8 + 4] = make_float4(xv[4],xv[5],0.f,0.f);
}

__global__ void k_esum1(const int* __restrict__ ei) {
    int e = blockIdx.x*blockDim.x + threadIdx.x;
    if (e >= ETOT) return;
    int s, d;
    if (e < N_EDGES) { s = ei[e]; d = ei[N_EDGES + e]; } else { s = d = e - N_EDGES; }
    float4 as = *(const float4*)&g_asrc1[s*4];
    float4 ad = *(const float4*)&g_adst1[d*4];
    float ex[4];
    ex[0] = expf(lrelu(as.x + ad.x));
    ex[1] = expf(lrelu(as.y + ad.y));
    ex[2] = expf(lrelu(as.z + ad.z));
    ex[3] = expf(lrelu(as.w + ad.w));
    float4 xa = *(const float4*)&g_x8[s*8];
    float4 xb = *(const float4*)&g_x8[s*8 + 4];
    float* base = &g_xagg[d*32];
    #pragma unroll
    for (int h = 0; h < 4; h++) {
        float w = ex[h];
        redAdd4(base + h*8,     w*xa.x, w*xa.y, w*xa.z, w*xa.w);
        redAdd4(base + h*8 + 4, w*xb.x, w*xb.y, w,      0.f);
    }
}

// fused: h1 = elu(bn(xagg@W1/denom)); hproj2 = h1@W2; att2 dots. 2 CTAs/SM.
#define P2N 32
__global__ void __launch_bounds__(256, 2) k_proj2f(
        const float* __restrict__ W1, const float* __restrict__ b1,
        const float* __restrict__ g1, const float* __restrict__ be1,
        const float* __restrict__ W2,
        const float* __restrict__ as2, const float* __restrict__ ad2) {
    extern __shared__ float sm[];
    float* W2p  = sm;                  // [128 k2][64 j][2] = 16384
    float* h1s  = sm + 16384;          // [32][258]
    float* xags = h1s + P2N*258;       // [32][32]
    int t = threadIdx.x;
    int nbase = blockIdx.x * P2N;

    for (int i = t; i < 16384; i += 256) {
        int k = i >> 6, j = i & 63;
        W2p[(k >> 1)*128 + j*2 + (k & 1)] = W2[i];
    }
    for (int i = t; i < P2N*32; i += 256) xags[i] = g_xagg[nbase*32 + i];
    __syncthreads();

    { // h1 tile: column c = t fixed per thread
        float w1r[6];
        #pragma unroll
        for (int k = 0; k < 6; k++) w1r[k] = W1[k*C1 + t];
        float b1r = b1[t], g1r = g1[t]*BN_INV, ber = be1[t];
        int h = t >> 6;
        #pragma unroll 4
        for (int n = 0; n < P2N; n++) {
            const float* xa = &xags[n*32 + h*8];
            float v = 0.f;
            #pragma unroll
            for (int k = 0; k < 6; k++) v += xa[k]*w1r[k];
            v = v/xa[6] + b1r;
            h1s[n*258 + t] = eluf(g1r*v + ber);
        }
    }
    __syncthreads();

    int cg = t & 15, ng = t >> 4;          // 16 col-groups x 16 node-groups (2 nodes each)
    int j0 = cg*4;
    unsigned long long acc[2][4];
    #pragma unroll
    for (int q = 0; q < 2; q++)
        #pragma unroll
        for (int j = 0; j < 4; j++) acc[q][j] = 0ull;

    #pragma unroll 4
    for (int k2 = 0; k2 < 128; k2++) {
        const float* wb = &W2p[k2*128 + j0*2];
        ulonglong2 w01 = *(const ulonglong2*)wb;
        ulonglong2 w23 = *(const ulonglong2*)(wb + 4);
        #pragma unroll
        for (int q = 0; q < 2; q++) {
            unsigned long long hv = *(const unsigned long long*)&h1s[(ng*2 + q)*258 + k2*2];
            ffma2(acc[q][0], hv, w01.x);
            ffma2(acc[q][1], hv, w01.y);
            ffma2(acc[q][2], hv, w23.x);
            ffma2(acc[q][3], hv, w23.y);
        }
    }

    float as2r[4], ad2r[4];
    #pragma unroll
    for (int j = 0; j < 4; j++) { as2r[j] = as2[j0+j]; ad2r[j] = ad2[j0+j]; }
    #pragma unroll
    for (int q = 0; q < 2; q++) {
        float o[4], s = 0.f, dd = 0.f;
        #pragma unroll
        for (int j = 0; j < 4; j++) {
            float2 u = unpk(acc[q][j]);
            o[j] = u.x + u.y;
            s  += o[j]*as2r[j];
            dd += o[j]*ad2r[j];
        }
        int n = nbase + ng*2 + q;
        *(float4*)&g_hproj2[n*64 + j0] = make_float4(o[0],o[1],o[2],o[3]);
        #pragma unroll
        for (int m = 1; m < 16; m <<= 1) {
            s  += __shfl_xor_sync(~0u, s,  m);
            dd += __shfl_xor_sync(~0u, dd, m);
        }
        if (cg == 0) { g_asrc2[n] = s; g_adst2[n] = dd; }
    }
}

// 8 threads/edge: denom += ex; accum2[dst] += ex*hproj2[src]
__global__ void k_esum2(const int* __restrict__ ei) {
    int gt = blockIdx.x*blockDim.x + threadIdx.x;
    int e = gt >> 3, q = gt & 7;
    if (e >= ETOT) return;
    int s, d;
    if (e < N_EDGES) { s = ei[e]; d = ei[N_EDGES + e]; } else { s = d = e - N_EDGES; }
    float ex = expf(lrelu(g_asrc2[s] + g_adst2[d]));
    if (q == 0) atomicAdd(&g_denom2[d], ex);
    int c = q*8;
    float4 v1 = *(const float4*)&g_hproj2[s*64 + c];
    float4 v2 = *(const float4*)&g_hproj2[s*64 + c + 4];
    redAdd4(&g_accum2[d*64 + c],     v1.x*ex, v1.y*ex, v1.z*ex, v1.w*ex);
    redAdd4(&g_accum2[d*64 + c + 4], v2.x*ex, v2.y*ex, v2.z*ex, v2.w*ex);
}

// fused: h2 = elu(bn(accum2/denom2)); xgates = h2@Wih^T + biases (scattered). 3 CTAs/SM.
#define XGN 16
__global__ void __launch_bounds__(256, 3) k_xgates2(
        const float* __restrict__ Wih, const float* __restrict__ bih,
        const float* __restrict__ bhh, const float* __restrict__ b2,
        const float* __restrict__ g2, const float* __restrict__ be2,
        const int* __restrict__ batch, const int* __restrict__ ntime) {
    extern __shared__ float sm[];
    float* WTp = sm;                   // [32 k2][256 j][2] = 16384
    float* h2s = sm + 16384;           // [16][66]
    int t = threadIdx.x;
    int nbase = blockIdx.x * XGN;

    for (int i = t; i < 16384; i += 256) {
        int j = i >> 6, k = i & 63;
        WTp[(k >> 1)*512 + j*2 + (k & 1)] = Wih[i];
    }
    {
        int k = t & 63;
        float b2r = b2[k], g2r = g2[k]*BN_INV, ber = be2[k];
        #pragma unroll
        for (int i = t; i < XGN*64; i += 256) {
            int n = i >> 6;
            float v = g_accum2[(nbase + n)*64 + k] / g_denom2[nbase + n] + b2r;
            h2s[n*66 + k] = eluf(g2r*v + ber);
        }
    }
    __syncthreads();

    int cg = t & 63, ng = t >> 6;      // 64 col-groups x 4 node-groups (4 nodes each)
    int j0 = cg*4;
    unsigned long long acc[4][4];
    #pragma unroll
    for (int q = 0; q < 4; q++)
        #pragma unroll
        for (int j = 0; j < 4; j++) acc[q][j] = 0ull;

    #pragma unroll 8
    for (int k2 = 0; k2 < 32; k2++) {
        const float* wb = &WTp[k2*512 + j0*2];
        ulonglong2 w01 = *(const ulonglong2*)wb;
        ulonglong2 w23 = *(const ulonglong2*)(wb + 4);
        #pragma unroll
        for (int q = 0; q < 4; q++) {
            unsigned long long hv = *(const unsigned long long*)&h2s[(ng*4 + q)*66 + k2*2];
            ffma2(acc[q][0], hv, w01.x);
            ffma2(acc[q][1], hv, w01.y);
            ffma2(acc[q][2], hv, w23.x);
            ffma2(acc[q][3], hv, w23.y);
        }
    }

    float4 bb;
    bb.x = bih[j0]   + bhh[j0];
    bb.y = bih[j0+1] + bhh[j0+1];
    bb.z = bih[j0+2] + bhh[j0+2];
    bb.w = bih[j0+3] + bhh[j0+3];
    #pragma unroll
    for (int q = 0; q < 4; q++) {
        int n = nbase + ng*4 + q;
        float2 u0 = unpk(acc[q][0]), u1 = unpk(acc[q][1]);
        float2 u2 = unpk(acc[q][2]), u3 = unpk(acc[q][3]);
        int dest = (ntime[n]*G_GRAPHS + batch[n])*C1 + j0;
        *(float4*)&g_xgates[dest] = make_float4(u0.x+u0.y+bb.x, u1.x+u1.y+bb.y,
                                                u2.x+u2.y+bb.z, u3.x+u3.y+bb.w);
    }
}

// LSTM: 1 graph/block (512 blocks), Whh row in regs, xgates prefetch, fused FC.
__global__ void __launch_bounds__(256) k_lstm(
        const float* __restrict__ Whh, const float* __restrict__ Wfc,
        const float* __restrict__ bfc, float* __restrict__ out) {
    __shared__ float hhs[64];
    __shared__ float gates[C1];
    int t = threadIdx.x;
    int g = blockIdx.x;

    unsigned long long w2[32];
    const float4* wrow = (const float4*)(Whh + t*64);
    #pragma unroll
    for (int i = 0; i < 16; i++) {
        float4 w = wrow[i];
        w2[2*i]   = pk(w.x, w.y);
        w2[2*i+1] = pk(w.z, w.w);
    }
    if (t < 64) hhs[t] = 0.f;
    float c = 0.f;
    float xg_cur = g_xgates[g*C1 + t];
    __syncthreads();

    for (int step = 0; step < T_STEPS; step++) {
        float xg_next = 0.f;
        if (step + 1 < T_STEPS) xg_next = g_xgates[((step+1)*G_GRAPHS + g)*C1 + t];
        unsigned long long aA = 0ull, aB = 0ull;
        #pragma unroll
        for (int k2 = 0; k2 < 16; k2++) {
            ulonglong2 hv = *(const ulonglong2*)&hhs[k2*4];
            ffma2(aA, hv.x, w2[2*k2]);
            ffma2(aB, hv.y, w2[2*k2+1]);
        }
        float2 a = unpk(aA), b = unpk(aB);
        gates[t] = xg_cur + a.x + a.y + b.x + b.y;
        __syncthreads();
        if (t < 64) {
            float ig = gates[t],       fg = gates[64 + t];
            float gg = gates[128 + t], og = gates[192 + t];
            c = sigf(fg)*c + sigf(ig)*tanhf(gg);
            hhs[t] = sigf(og)*tanhf(c);
        }
        __syncthreads();
        xg_cur = xg_next;
    }
    if (t < OUT_DIM) {
        float acc = bfc[t];
        #pragma unroll 8
        for (int k = 0; k < 64; k++) acc += hhs[k] * Wfc[k*OUT_DIM + t];
        out[g*OUT_DIM + t] = acc;
    }
}

// ---------------- launch ----------------
static const int SMEM_P2 = (16384 + P2N*258 + P2N*32) * 4;   // ~102.7 KB
static const int SMEM_XG = (16384 + XGN*66) * 4;             // ~69.8 KB

extern "C" void kernel_launch(void* const* d_in, const int* in_sizes, int n_in,
                              void* d_out, int out_size) {
    const float* x    = (const float*)d_in[0];
    const int*   ei   = (const int*)  d_in[1];
    const int*   batch= (const int*)  d_in[2];
    const int*   ntime= (const int*)  d_in[3];
    const float* W1   = (const float*)d_in[4];
    const float* as1  = (const float*)d_in[5];
    const float* ad1  = (const float*)d_in[6];
    const float* b1   = (const float*)d_in[7];
    const float* g1   = (const float*)d_in[8];
    const float* be1  = (const float*)d_in[9];
    const float* W2   = (const float*)d_in[10];
    const float* as2  = (const float*)d_in[11];
    const float* ad2  = (const float*)d_in[12];
    const float* b2   = (const float*)d_in[13];
    const float* g2   = (const float*)d_in[14];
    const float* be2  = (const float*)d_in[15];
    const float* Wih  = (const float*)d_in[16];
    const float* Whh  = (const float*)d_in[17];
    const float* bih  = (const float*)d_in[18];
    const float* bhh  = (const float*)d_in[19];
    const float* Wfc  = (const float*)d_in[20];
    const float* bfc  = (const float*)d_in[21];
    float* out = (float*)d_out;

    cudaFuncSetAttribute(k_proj2f,  cudaFuncAttributeMaxDynamicSharedMemorySize, SMEM_P2);
    cudaFuncSetAttribute(k_xgates2, cudaFuncAttributeMaxDynamicSharedMemorySize, SMEM_XG);

    void *p_xagg, *p_acc2, *p_den2;
    cudaGetSymbolAddress(&p_xagg, g_xagg);
    cudaGetSymbolAddress(&p_acc2, g_accum2);
    cudaGetSymbolAddress(&p_den2, g_denom2);
    cudaMemsetAsync(p_xagg, 0, sizeof(float)*N_NODES*32);
    cudaMemsetAsync(p_acc2, 0, sizeof(float)*N_NODES*HID);
    cudaMemsetAsync(p_den2, 0, sizeof(float)*N_NODES);

    k_pre1   <<<1, 64>>>(W1, as1, ad1);
    k_att1   <<<(N_NODES + 255)/256, 256>>>(x);
    k_esum1  <<<(ETOT + 255)/256, 256>>>(ei);
    k_proj2f <<<N_NODES/P2N, 256, SMEM_P2>>>(W1, b1, g1, be1, W2, as2, ad2);
    k_esum2  <<<(ETOT*8 + 255)/256, 256>>>(ei);
    k_xgates2<<<N_NODES/XGN, 256, SMEM_XG>>>(Wih, bih, bhh, b2, g2, be2, batch, ntime);
    k_lstm   <<<G_GRAPHS, 256>>>(Whh, Wfc, bfc, out);
}

// round 5
// speedup vs baseline: 1.1026x; 1.1026x over previous
#include <cuda_runtime.h>
#include <math.h>

#define N_NODES 25600
#define N_EDGES 204800
#define ETOT    (N_EDGES + N_NODES)   // 230400
#define IN_CH   6
#define HID     64
#define HEADS   4
#define C1      (HEADS*HID)           // 256
#define G_GRAPHS 512
#define T_STEPS  50
#define OUT_DIM  30
#define NEG_SLOPE 0.2f
#define BN_INV 0.9999950000374996f    // 1/sqrt(1+1e-5)

// ---------------- scratch ----------------
__device__ float g_wsrc[24];                  // [k][h]
__device__ float g_wdst[24];
__device__ __align__(16) float g_x8[N_NODES*8];       // padded x rows
__device__ __align__(16) float g_asrc1[N_NODES*4];
__device__ __align__(16) float g_adst1[N_NODES*4];
__device__ __align__(16) float g_xagg[N_NODES*32];    // 4 heads x [x0..x5, denom, 0]
__device__ __align__(16) float g_hproj2[N_NODES*HID];
__device__ float g_asrc2[N_NODES];
__device__ float g_adst2[N_NODES];
__device__ float g_denom2[N_NODES];
__device__ __align__(16) float g_accum2[N_NODES*HID];
__device__ __align__(16) float g_xgates[N_NODES*C1];  // (t, g, 256)

// ---------------- helpers ----------------
__device__ __forceinline__ float lrelu(float v) { return v > 0.f ? v : NEG_SLOPE*v; }
__device__ __forceinline__ float eluf(float v)  { return v > 0.f ? v : expm1f(v); }
__device__ __forceinline__ float sigf(float v)  { return 1.f/(1.f+expf(-v)); }

__device__ __forceinline__ void redAdd4(float* addr, float a, float b, float c, float d) {
    asm volatile("red.global.add.v4.f32 [%0], {%1,%2,%3,%4};"
                 :: "l"(addr), "f"(a), "f"(b), "f"(c), "f"(d) : "memory");
}
__device__ __forceinline__ void ffma2(unsigned long long& d, unsigned long long a,
                                      unsigned long long b) {
    asm("fma.rn.f32x2 %0, %1, %2, %0;" : "+l"(d) : "l"(a), "l"(b));
}
__device__ __forceinline__ unsigned long long pk(float a, float b) {
    unsigned long long r;
    asm("mov.b64 %0, {%1, %2};" : "=l"(r) : "f"(a), "f"(b));
    return r;
}
__device__ __forceinline__ float2 unpk(unsigned long long v) {
    float2 r;
    asm("mov.b64 {%0, %1}, %2;" : "=f"(r.x), "=f"(r.y) : "l"(v));
    return r;
}

// ---------------- kernels ----------------
__global__ void k_pre1(const float* __restrict__ W1, const float* __restrict__ as1,
                       const float* __restrict__ ad1) {
    int t = threadIdx.x;
    if (t < 24) {
        int k = t >> 2, h = t & 3;
        float s = 0.f;
        for (int c = 0; c < 64; c++) s += W1[k*C1 + h*64 + c] * as1[h*64 + c];
        g_wsrc[t] = s;
    } else if (t >= 32 && t < 56) {
        int i = t - 32, k = i >> 2, h = i & 3;
        float s = 0.f;
        for (int c = 0; c < 64; c++) s += W1[k*C1 + h*64 + c] * ad1[h*64 + c];
        g_wdst[i] = s;
    }
}

__global__ void k_att1(const float* __restrict__ x) {
    int n = blockIdx.x*blockDim.x + threadIdx.x;
    if (n >= N_NODES) return;
    float2 xa = *(const float2*)&x[n*6];
    float2 xb = *(const float2*)&x[n*6 + 2];
    float2 xc = *(const float2*)&x[n*6 + 4];
    float xv[6] = {xa.x, xa.y, xb.x, xb.y, xc.x, xc.y};
    float s[4] = {0,0,0,0}, d[4] = {0,0,0,0};
    #pragma unroll
    for (int k = 0; k < 6; k++) {
        #pragma unroll
        for (int h = 0; h < 4; h++) {
            s[h] += xv[k]*g_wsrc[k*4+h];
            d[h] += xv[k]*g_wdst[k*4+h];
        }
    }
    *(float4*)&g_asrc1[n*4] = make_float4(s[0],s[1],s[2],s[3]);
    *(float4*)&g_adst1[n*4] = make_float4(d[0],d[1],d[2],d[3]);
    *(float4*)&g_x8[n*8]     = make_float4(xv[0],xv[1],xv[2],xv[3]);
    *(float4*)&g_x8[n*8 + 4] = make_float4(xv[4],xv[5],0.f,0.f);
}

__global__ void k_esum1(const int* __restrict__ ei) {
    int e = blockIdx.x*blockDim.x + threadIdx.x;
    if (e >= ETOT) return;
    int s, d;
    if (e < N_EDGES) { s = ei[e]; d = ei[N_EDGES + e]; } else { s = d = e - N_EDGES; }
    float4 as = *(const float4*)&g_asrc1[s*4];
    float4 ad = *(const float4*)&g_adst1[d*4];
    float ex[4];
    ex[0] = expf(lrelu(as.x + ad.x));
    ex[1] = expf(lrelu(as.y + ad.y));
    ex[2] = expf(lrelu(as.z + ad.z));
    ex[3] = expf(lrelu(as.w + ad.w));
    float4 xa = *(const float4*)&g_x8[s*8];
    float4 xb = *(const float4*)&g_x8[s*8 + 4];
    float* base = &g_xagg[d*32];
    #pragma unroll
    for (int h = 0; h < 4; h++) {
        float w = ex[h];
        redAdd4(base + h*8,     w*xa.x, w*xa.y, w*xa.z, w*xa.w);
        redAdd4(base + h*8 + 4, w*xb.x, w*xb.y, w,      0.f);
    }
}

// fused: h1 = elu(bn(xagg@W1/denom)); hproj2 = h1@W2; att2 dots. 2 CTAs/SM.
// Weight smem layout (conflict-free): W2p[(k>>1)*128 + (j>>2)*8 + (j&3)*2 + (k&1)]
#define P2N 32
__global__ void __launch_bounds__(256, 2) k_proj2f(
        const float* __restrict__ W1, const float* __restrict__ b1,
        const float* __restrict__ g1, const float* __restrict__ be1,
        const float* __restrict__ W2,
        const float* __restrict__ as2, const float* __restrict__ ad2) {
    extern __shared__ float sm[];
    float* W2p  = sm;                  // 16384
    float* h1s  = sm + 16384;          // [32][258]
    float* xags = h1s + P2N*258;       // [32][32]
    int t = threadIdx.x;
    int nbase = blockIdx.x * P2N;

    for (int i = t; i < 16384; i += 256) {
        int k = i >> 6, j = i & 63;
        W2p[(k >> 1)*128 + (j >> 2)*8 + (j & 3)*2 + (k & 1)] = W2[i];
    }
    for (int i = t; i < P2N*32; i += 256) xags[i] = g_xagg[nbase*32 + i];
    __syncthreads();

    { // h1 tile: column c = t fixed per thread
        float w1r[6];
        #pragma unroll
        for (int k = 0; k < 6; k++) w1r[k] = W1[k*C1 + t];
        float b1r = b1[t], g1r = g1[t]*BN_INV, ber = be1[t];
        int h = t >> 6;
        #pragma unroll 4
        for (int n = 0; n < P2N; n++) {
            const float* xa = &xags[n*32 + h*8];
            float v = 0.f;
            #pragma unroll
            for (int k = 0; k < 6; k++) v += xa[k]*w1r[k];
            v = v/xa[6] + b1r;
            h1s[n*258 + t] = eluf(g1r*v + ber);
        }
    }
    __syncthreads();

    int cg = t & 15, ng = t >> 4;          // 16 col-groups x 16 node-groups (2 nodes each)
    int j0 = cg*4;
    unsigned long long acc[2][4];
    #pragma unroll
    for (int q = 0; q < 2; q++)
        #pragma unroll
        for (int j = 0; j < 4; j++) acc[q][j] = 0ull;

    const float* wbase = &W2p[cg*8];
    const float* hbase = &h1s[(ng*2)*258];
    #pragma unroll 8
    for (int k2 = 0; k2 < 128; k2++) {
        ulonglong2 w01 = *(const ulonglong2*)(wbase + k2*128);
        ulonglong2 w23 = *(const ulonglong2*)(wbase + k2*128 + 4);
        #pragma unroll
        for (int q = 0; q < 2; q++) {
            unsigned long long hv = *(const unsigned long long*)(hbase + q*258 + k2*2);
            ffma2(acc[q][0], hv, w01.x);
            ffma2(acc[q][1], hv, w01.y);
            ffma2(acc[q][2], hv, w23.x);
            ffma2(acc[q][3], hv, w23.y);
        }
    }

    float as2r[4], ad2r[4];
    #pragma unroll
    for (int j = 0; j < 4; j++) { as2r[j] = as2[j0+j]; ad2r[j] = ad2[j0+j]; }
    #pragma unroll
    for (int q = 0; q < 2; q++) {
        float o[4], s = 0.f, dd = 0.f;
        #pragma unroll
        for (int j = 0; j < 4; j++) {
            float2 u = unpk(acc[q][j]);
            o[j] = u.x + u.y;
            s  += o[j]*as2r[j];
            dd += o[j]*ad2r[j];
        }
        int n = nbase + ng*2 + q;
        *(float4*)&g_hproj2[n*64 + j0] = make_float4(o[0],o[1],o[2],o[3]);
        #pragma unroll
        for (int m = 1; m < 16; m <<= 1) {
            s  += __shfl_xor_sync(~0u, s,  m);
            dd += __shfl_xor_sync(~0u, dd, m);
        }
        if (cg == 0) { g_asrc2[n] = s; g_adst2[n] = dd; }
    }
}

// 8 threads/edge: denom += ex; accum2[dst] += ex*hproj2[src]
__global__ void k_esum2(const int* __restrict__ ei) {
    int gt = blockIdx.x*blockDim.x + threadIdx.x;
    int e = gt >> 3, q = gt & 7;
    if (e >= ETOT) return;
    int s, d;
    if (e < N_EDGES) { s = ei[e]; d = ei[N_EDGES + e]; } else { s = d = e - N_EDGES; }
    float ex = expf(lrelu(g_asrc2[s] + g_adst2[d]));
    if (q == 0) atomicAdd(&g_denom2[d], ex);
    int c = q*8;
    float4 v1 = *(const float4*)&g_hproj2[s*64 + c];
    float4 v2 = *(const float4*)&g_hproj2[s*64 + c + 4];
    redAdd4(&g_accum2[d*64 + c],     v1.x*ex, v1.y*ex, v1.z*ex, v1.w*ex);
    redAdd4(&g_accum2[d*64 + c + 4], v2.x*ex, v2.y*ex, v2.z*ex, v2.w*ex);
}

// fused: h2 = elu(bn(accum2/denom2)); xgates = h2@Wih^T + biases (scattered). 2 CTAs/SM.
// Weight smem layout (conflict-free): WTp[(k>>1)*512 + (j>>2)*8 + (j&3)*2 + (k&1)]
#define XGN 32
__global__ void __launch_bounds__(256, 2) k_xgates2(
        const float* __restrict__ Wih, const float* __restrict__ bih,
        const float* __restrict__ bhh, const float* __restrict__ b2,
        const float* __restrict__ g2, const float* __restrict__ be2,
        const int* __restrict__ batch, const int* __restrict__ ntime) {
    extern __shared__ float sm[];
    float* WTp = sm;                   // 16384
    float* h2s = sm + 16384;           // [32][66]
    int t = threadIdx.x;
    int nbase = blockIdx.x * XGN;

    for (int i = t; i < 16384; i += 256) {
        int j = i >> 6, k = i & 63;     // Wih row j (gate col), col k
        WTp[(k >> 1)*512 + (j >> 2)*8 + (j & 3)*2 + (k & 1)] = Wih[i];
    }
    {
        int k = t & 63;
        float b2r = b2[k], g2r = g2[k]*BN_INV, ber = be2[k];
        #pragma unroll
        for (int i = t; i < XGN*64; i += 256) {
            int n = i >> 6;
            float v = g_accum2[(nbase + n)*64 + k] / g_denom2[nbase + n] + b2r;
            h2s[n*66 + k] = eluf(g2r*v + ber);
        }
    }
    __syncthreads();

    int cg = t & 63, ng = t >> 6;      // 64 col-groups x 4 node-groups (8 nodes each)
    int j0 = cg*4;
    unsigned long long acc[8][4];
    #pragma unroll
    for (int q = 0; q < 8; q++)
        #pragma unroll
        for (int j = 0; j < 4; j++) acc[q][j] = 0ull;

    const float* wbase = &WTp[cg*8];
    const float* hbase = &h2s[(ng*8)*66];
    #pragma unroll 4
    for (int k2 = 0; k2 < 32; k2++) {
        ulonglong2 w01 = *(const ulonglong2*)(wbase + k2*512);
        ulonglong2 w23 = *(const ulonglong2*)(wbase + k2*512 + 4);
        #pragma unroll
        for (int q = 0; q < 8; q++) {
            unsigned long long hv = *(const unsigned long long*)(hbase + q*66 + k2*2);
            ffma2(acc[q][0], hv, w01.x);
            ffma2(acc[q][1], hv, w01.y);
            ffma2(acc[q][2], hv, w23.x);
            ffma2(acc[q][3], hv, w23.y);
        }
    }

    float4 bb;
    bb.x = bih[j0]   + bhh[j0];
    bb.y = bih[j0+1] + bhh[j0+1];
    bb.z = bih[j0+2] + bhh[j0+2];
    bb.w = bih[j0+3] + bhh[j0+3];
    #pragma unroll
    for (int q = 0; q < 8; q++) {
        int n = nbase + ng*8 + q;
        float2 u0 = unpk(acc[q][0]), u1 = unpk(acc[q][1]);
        float2 u2 = unpk(acc[q][2]), u3 = unpk(acc[q][3]);
        int dest = (ntime[n]*G_GRAPHS + batch[n])*C1 + j0;
        *(float4*)&g_xgates[dest] = make_float4(u0.x+u0.y+bb.x, u1.x+u1.y+bb.y,
                                                u2.x+u2.y+bb.z, u3.x+u3.y+bb.w);
    }
}

// LSTM: 1 graph/block (512 blocks), Whh row in regs, xgates prefetch, fused FC.
__global__ void __launch_bounds__(256) k_lstm(
        const float* __restrict__ Whh, const float* __restrict__ Wfc,
        const float* __restrict__ bfc, float* __restrict__ out) {
    __shared__ float hhs[64];
    __shared__ float gates[C1];
    int t = threadIdx.x;
    int g = blockIdx.x;

    unsigned long long w2[32];
    const float4* wrow = (const float4*)(Whh + t*64);
    #pragma unroll
    for (int i = 0; i < 16; i++) {
        float4 w = wrow[i];
        w2[2*i]   = pk(w.x, w.y);
        w2[2*i+1] = pk(w.z, w.w);
    }
    if (t < 64) hhs[t] = 0.f;
    float c = 0.f;
    float xg_cur = g_xgates[g*C1 + t];
    __syncthreads();

    for (int step = 0; step < T_STEPS; step++) {
        float xg_next = 0.f;
        if (step + 1 < T_STEPS) xg_next = g_xgates[((step+1)*G_GRAPHS + g)*C1 + t];
        unsigned long long aA = 0ull, aB = 0ull;
        #pragma unroll
        for (int k2 = 0; k2 < 16; k2++) {
            ulonglong2 hv = *(const ulonglong2*)&hhs[k2*4];
            ffma2(aA, hv.x, w2[2*k2]);
            ffma2(aB, hv.y, w2[2*k2+1]);
        }
        float2 a = unpk(aA), b = unpk(aB);
        gates[t] = xg_cur + a.x + a.y + b.x + b.y;
        __syncthreads();
        if (t < 64) {
            float ig = gates[t],       fg = gates[64 + t];
            float gg = gates[128 + t], og = gates[192 + t];
            c = sigf(fg)*c + sigf(ig)*tanhf(gg);
            hhs[t] = sigf(og)*tanhf(c);
        }
        __syncthreads();
        xg_cur = xg_next;
    }
    if (t < OUT_DIM) {
        float acc = bfc[t];
        #pragma unroll 8
        for (int k = 0; k < 64; k++) acc += hhs[k] * Wfc[k*OUT_DIM + t];
        out[g*OUT_DIM + t] = acc;
    }
}

// ---------------- launch ----------------
static const int SMEM_P2 = (16384 + P2N*258 + P2N*32) * 4;   // ~102.7 KB
static const int SMEM_XG = (16384 + XGN*66) * 4;             // ~74 KB

extern "C" void kernel_launch(void* const* d_in, const int* in_sizes, int n_in,
                              void* d_out, int out_size) {
    const float* x    = (const float*)d_in[0];
    const int*   ei   = (const int*)  d_in[1];
    const int*   batch= (const int*)  d_in[2];
    const int*   ntime= (const int*)  d_in[3];
    const float* W1   = (const float*)d_in[4];
    const float* as1  = (const float*)d_in[5];
    const float* ad1  = (const float*)d_in[6];
    const float* b1   = (const float*)d_in[7];
    const float* g1   = (const float*)d_in[8];
    const float* be1  = (const float*)d_in[9];
    const float* W2   = (const float*)d_in[10];
    const float* as2  = (const float*)d_in[11];
    const float* ad2  = (const float*)d_in[12];
    const float* b2   = (const float*)d_in[13];
    const float* g2   = (const float*)d_in[14];
    const float* be2  = (const float*)d_in[15];
    const float* Wih  = (const float*)d_in[16];
    const float* Whh  = (const float*)d_in[17];
    const float* bih  = (const float*)d_in[18];
    const float* bhh  = (const float*)d_in[19];
    const float* Wfc  = (const float*)d_in[20];
    const float* bfc  = (const float*)d_in[21];
    float* out = (float*)d_out;

    cudaFuncSetAttribute(k_proj2f,  cudaFuncAttributeMaxDynamicSharedMemorySize, SMEM_P2);
    cudaFuncSetAttribute(k_xgates2, cudaFuncAttributeMaxDynamicSharedMemorySize, SMEM_XG);

    void *p_xagg, *p_acc2, *p_den2;
    cudaGetSymbolAddress(&p_xagg, g_xagg);
    cudaGetSymbolAddress(&p_acc2, g_accum2);
    cudaGetSymbolAddress(&p_den2, g_denom2);
    cudaMemsetAsync(p_xagg, 0, sizeof(float)*N_NODES*32);
    cudaMemsetAsync(p_acc2, 0, sizeof(float)*N_NODES*HID);
    cudaMemsetAsync(p_den2, 0, sizeof(float)*N_NODES);

    k_pre1   <<<1, 64>>>(W1, as1, ad1);
    k_att1   <<<(N_NODES + 255)/256, 256>>>(x);
    k_esum1  <<<(ETOT + 255)/256, 256>>>(ei);
    k_proj2f <<<N_NODES/P2N, 256, SMEM_P2>>>(W1, b1, g1, be1, W2, as2, ad2);
    k_esum2  <<<(ETOT*8 + 255)/256, 256>>>(ei);
    k_xgates2<<<N_NODES/XGN, 256, SMEM_XG>>>(Wih, bih, bhh, b2, g2, be2, batch, ntime);
    k_lstm   <<<G_GRAPHS, 256>>>(Whh, Wfc, bfc, out);
}

// round 6
// speedup vs baseline: 1.1386x; 1.0327x over previous
#include <cuda_runtime.h>
#include <math.h>

#define N_NODES 25600
#define N_EDGES 204800
#define ETOT    (N_EDGES + N_NODES)   // 230400
#define IN_CH   6
#define HID     64
#define HEADS   4
#define C1      (HEADS*HID)           // 256
#define G_GRAPHS 512
#define T_STEPS  50
#define OUT_DIM  30
#define NEG_SLOPE 0.2f
#define BN_INV 0.9999950000374996f    // 1/sqrt(1+1e-5)

// ---------------- scratch ----------------
__device__ float g_wsrc[24];                  // [k][h]
__device__ float g_wdst[24];
__device__ __align__(16) float g_x8[N_NODES*8];       // padded x rows
__device__ __align__(16) float g_asrc1[N_NODES*4];
__device__ __align__(16) float g_adst1[N_NODES*4];
__device__ __align__(16) float g_xagg[N_NODES*32];    // 4 heads x [x0..x5, denom, 0]
__device__ __align__(16) float g_hproj2[N_NODES*HID];
__device__ float g_asrc2[N_NODES];
__device__ float g_adst2[N_NODES];
__device__ float g_denom2[N_NODES];
__device__ __align__(16) float g_accum2[N_NODES*HID];
__device__ __align__(16) float g_xgates[N_NODES*C1];  // (t, g, 256)

// ---------------- helpers ----------------
__device__ __forceinline__ float lrelu(float v) { return v > 0.f ? v : NEG_SLOPE*v; }
__device__ __forceinline__ float eluf(float v)  { return v > 0.f ? v : expm1f(v); }
__device__ __forceinline__ float sigf(float v)  { return 1.f/(1.f+expf(-v)); }

__device__ __forceinline__ void redAdd4(float* addr, float a, float b, float c, float d) {
    asm volatile("red.global.add.v4.f32 [%0], {%1,%2,%3,%4};"
                 :: "l"(addr), "f"(a), "f"(b), "f"(c), "f"(d) : "memory");
}
__device__ __forceinline__ void ffma2(unsigned long long& d, unsigned long long a,
                                      unsigned long long b) {
    asm("fma.rn.f32x2 %0, %1, %2, %0;" : "+l"(d) : "l"(a), "l"(b));
}
__device__ __forceinline__ unsigned long long pk(float a, float b) {
    unsigned long long r;
    asm("mov.b64 %0, {%1, %2};" : "=l"(r) : "f"(a), "f"(b));
    return r;
}
__device__ __forceinline__ float2 unpk(unsigned long long v) {
    float2 r;
    asm("mov.b64 {%0, %1}, %2;" : "=f"(r.x), "=f"(r.y) : "l"(v));
    return r;
}

// ---------------- kernels ----------------
__global__ void k_pre1(const float* __restrict__ W1, const float* __restrict__ as1,
                       const float* __restrict__ ad1) {
    int t = threadIdx.x;
    if (t < 24) {
        int k = t >> 2, h = t & 3;
        float s = 0.f;
        for (int c = 0; c < 64; c++) s += W1[k*C1 + h*64 + c] * as1[h*64 + c];
        g_wsrc[t] = s;
    } else if (t >= 32 && t < 56) {
        int i = t - 32, k = i >> 2, h = i & 3;
        float s = 0.f;
        for (int c = 0; c < 64; c++) s += W1[k*C1 + h*64 + c] * ad1[h*64 + c];
        g_wdst[i] = s;
    }
}

__global__ void k_att1(const float* __restrict__ x) {
    int n = blockIdx.x*blockDim.x + threadIdx.x;
    if (n >= N_NODES) return;
    float2 xa = *(const float2*)&x[n*6];
    float2 xb = *(const float2*)&x[n*6 + 2];
    float2 xc = *(const float2*)&x[n*6 + 4];
    float xv[6] = {xa.x, xa.y, xb.x, xb.y, xc.x, xc.y};
    float s[4] = {0,0,0,0}, d[4] = {0,0,0,0};
    #pragma unroll
    for (int k = 0; k < 6; k++) {
        #pragma unroll
        for (int h = 0; h < 4; h++) {
            s[h] += xv[k]*g_wsrc[k*4+h];
            d[h] += xv[k]*g_wdst[k*4+h];
        }
    }
    *(float4*)&g_asrc1[n*4] = make_float4(s[0],s[1],s[2],s[3]);
    *(float4*)&g_adst1[n*4] = make_float4(d[0],d[1],d[2],d[3]);
    *(float4*)&g_x8[n*8]     = make_float4(xv[0],xv[1],xv[2],xv[3]);
    *(float4*)&g_x8[n*8 + 4] = make_float4(xv[4],xv[5],0.f,0.f);
}

__global__ void k_esum1(const int* __restrict__ ei) {
    int e = blockIdx.x*blockDim.x + threadIdx.x;
    if (e >= ETOT) return;
    int s, d;
    if (e < N_EDGES) { s = ei[e]; d = ei[N_EDGES + e]; } else { s = d = e - N_EDGES; }
    float4 as = *(const float4*)&g_asrc1[s*4];
    float4 ad = *(const float4*)&g_adst1[d*4];
    float ex[4];
    ex[0] = expf(lrelu(as.x + ad.x));
    ex[1] = expf(lrelu(as.y + ad.y));
    ex[2] = expf(lrelu(as.z + ad.z));
    ex[3] = expf(lrelu(as.w + ad.w));
    float4 xa = *(const float4*)&g_x8[s*8];
    float4 xb = *(const float4*)&g_x8[s*8 + 4];
    float* base = &g_xagg[d*32];
    #pragma unroll
    for (int h = 0; h < 4; h++) {
        float w = ex[h];
        redAdd4(base + h*8,     w*xa.x, w*xa.y, w*xa.z, w*xa.w);
        redAdd4(base + h*8 + 4, w*xb.x, w*xb.y, w,      0.f);
    }
}

// fused: h1 = elu(bn(xagg@W1/denom)); hproj2 = h1@W2; att2 dots. 2 CTAs/SM.
// Per-thread tile: 4 nodes x 4 cols; 4 k's per inner step; LDS.128 everywhere.
#define P2N 64
__global__ void __launch_bounds__(256, 2) k_proj2f(
        const float* __restrict__ W1, const float* __restrict__ b1,
        const float* __restrict__ g1, const float* __restrict__ be1,
        const float* __restrict__ W2,
        const float* __restrict__ as2, const float* __restrict__ ad2) {
    extern __shared__ float sm[];
    float* W2p  = sm;                  // 16384 (packed pairs, conflict-free)
    float* h1s  = sm + 16384;          // [64][260] (16B-aligned rows)
    float* xags = h1s + P2N*260;       // [64][32]
    int t = threadIdx.x;
    int nbase = blockIdx.x * P2N;

    for (int i = t; i < 16384; i += 256) {
        int k = i >> 6, j = i & 63;
        W2p[(k >> 1)*128 + (j >> 2)*8 + (j & 3)*2 + (k & 1)] = W2[i];
    }
    for (int i = t; i < P2N*32; i += 256) xags[i] = g_xagg[nbase*32 + i];
    __syncthreads();

    { // h1 tile: column c = t fixed per thread
        float w1r[6];
        #pragma unroll
        for (int k = 0; k < 6; k++) w1r[k] = W1[k*C1 + t];
        float b1r = b1[t], g1r = g1[t]*BN_INV, ber = be1[t];
        int h = t >> 6;
        #pragma unroll 4
        for (int n = 0; n < P2N; n++) {
            const float* xa = &xags[n*32 + h*8];
            float v = 0.f;
            #pragma unroll
            for (int k = 0; k < 6; k++) v += xa[k]*w1r[k];
            v = v/xa[6] + b1r;
            h1s[n*260 + t] = eluf(g1r*v + ber);
        }
    }
    __syncthreads();

    int cg = t & 15, ng = t >> 4;          // 16 col-groups x 16 node-groups (4 nodes)
    int j0 = cg*4;
    unsigned long long acc[4][4];
    #pragma unroll
    for (int q = 0; q < 4; q++)
        #pragma unroll
        for (int j = 0; j < 4; j++) acc[q][j] = 0ull;

    const float* wbase = &W2p[cg*8];
    const float* hbase = &h1s[(ng*4)*260];
    #pragma unroll 4
    for (int kk = 0; kk < 64; kk++) {      // 4 k's per step
        ulonglong2 wa01 = *(const ulonglong2*)(wbase + (2*kk)*128);
        ulonglong2 wa23 = *(const ulonglong2*)(wbase + (2*kk)*128 + 4);
        ulonglong2 wb01 = *(const ulonglong2*)(wbase + (2*kk+1)*128);
        ulonglong2 wb23 = *(const ulonglong2*)(wbase + (2*kk+1)*128 + 4);
        #pragma unroll
        for (int q = 0; q < 4; q++) {
            ulonglong2 hv = *(const ulonglong2*)(hbase + q*260 + kk*4);
            ffma2(acc[q][0], hv.x, wa01.x);
            ffma2(acc[q][1], hv.x, wa01.y);
            ffma2(acc[q][2], hv.x, wa23.x);
            ffma2(acc[q][3], hv.x, wa23.y);
            ffma2(acc[q][0], hv.y, wb01.x);
            ffma2(acc[q][1], hv.y, wb01.y);
            ffma2(acc[q][2], hv.y, wb23.x);
            ffma2(acc[q][3], hv.y, wb23.y);
        }
    }

    float as2r[4], ad2r[4];
    #pragma unroll
    for (int j = 0; j < 4; j++) { as2r[j] = as2[j0+j]; ad2r[j] = ad2[j0+j]; }
    #pragma unroll
    for (int q = 0; q < 4; q++) {
        float o[4], s = 0.f, dd = 0.f;
        #pragma unroll
        for (int j = 0; j < 4; j++) {
            float2 u = unpk(acc[q][j]);
            o[j] = u.x + u.y;
            s  += o[j]*as2r[j];
            dd += o[j]*ad2r[j];
        }
        int n = nbase + ng*4 + q;
        *(float4*)&g_hproj2[n*64 + j0] = make_float4(o[0],o[1],o[2],o[3]);
        #pragma unroll
        for (int m = 1; m < 16; m <<= 1) {
            s  += __shfl_xor_sync(~0u, s,  m);
            dd += __shfl_xor_sync(~0u, dd, m);
        }
        if (cg == 0) { g_asrc2[n] = s; g_adst2[n] = dd; }
    }
}

// 8 threads/edge: denom += ex; accum2[dst] += ex*hproj2[src]
__global__ void k_esum2(const int* __restrict__ ei) {
    int gt = blockIdx.x*blockDim.x + threadIdx.x;
    int e = gt >> 3, q = gt & 7;
    if (e >= ETOT) return;
    int s, d;
    if (e < N_EDGES) { s = ei[e]; d = ei[N_EDGES + e]; } else { s = d = e - N_EDGES; }
    float ex = expf(lrelu(g_asrc2[s] + g_adst2[d]));
    if (q == 0) atomicAdd(&g_denom2[d], ex);
    int c = q*8;
    float4 v1 = *(const float4*)&g_hproj2[s*64 + c];
    float4 v2 = *(const float4*)&g_hproj2[s*64 + c + 4];
    redAdd4(&g_accum2[d*64 + c],     v1.x*ex, v1.y*ex, v1.z*ex, v1.w*ex);
    redAdd4(&g_accum2[d*64 + c + 4], v2.x*ex, v2.y*ex, v2.z*ex, v2.w*ex);
}

// fused: h2 = elu(bn(accum2/denom2)); xgates = h2@Wih^T + biases (scattered). 2 CTAs/SM.
// Per-thread tile: 8 nodes x 4 cols; 4 k's per inner step.
#define XGN 32
__global__ void __launch_bounds__(256, 2) k_xgates2(
        const float* __restrict__ Wih, const float* __restrict__ bih,
        const float* __restrict__ bhh, const float* __restrict__ b2,
        const float* __restrict__ g2, const float* __restrict__ be2,
        const int* __restrict__ batch, const int* __restrict__ ntime) {
    extern __shared__ float sm[];
    float* WTp = sm;                   // 16384
    float* h2s = sm + 16384;           // [32][68] (16B-aligned rows)
    int t = threadIdx.x;
    int nbase = blockIdx.x * XGN;

    for (int i = t; i < 16384; i += 256) {
        int j = i >> 6, k = i & 63;     // Wih row j (gate col), col k
        WTp[(k >> 1)*512 + (j >> 2)*8 + (j & 3)*2 + (k & 1)] = Wih[i];
    }
    {
        int k = t & 63;
        float b2r = b2[k], g2r = g2[k]*BN_INV, ber = be2[k];
        #pragma unroll
        for (int i = t; i < XGN*64; i += 256) {
            int n = i >> 6;
            float v = g_accum2[(nbase + n)*64 + k] / g_denom2[nbase + n] + b2r;
            h2s[n*68 + k] = eluf(g2r*v + ber);
        }
    }
    __syncthreads();

    int cg = t & 63, ng = t >> 6;      // 64 col-groups x 4 node-groups (8 nodes each)
    int j0 = cg*4;
    unsigned long long acc[8][4];
    #pragma unroll
    for (int q = 0; q < 8; q++)
        #pragma unroll
        for (int j = 0; j < 4; j++) acc[q][j] = 0ull;

    const float* wbase = &WTp[cg*8];
    const float* hbase = &h2s[(ng*8)*68];
    #pragma unroll 2
    for (int kk = 0; kk < 16; kk++) {      // 4 k's per step
        ulonglong2 wa01 = *(const ulonglong2*)(wbase + (2*kk)*512);
        ulonglong2 wa23 = *(const ulonglong2*)(wbase + (2*kk)*512 + 4);
        ulonglong2 wb01 = *(const ulonglong2*)(wbase + (2*kk+1)*512);
        ulonglong2 wb23 = *(const ulonglong2*)(wbase + (2*kk+1)*512 + 4);
        #pragma unroll
        for (int q = 0; q < 8; q++) {
            ulonglong2 hv = *(const ulonglong2*)(hbase + q*68 + kk*4);
            ffma2(acc[q][0], hv.x, wa01.x);
            ffma2(acc[q][1], hv.x, wa01.y);
            ffma2(acc[q][2], hv.x, wa23.x);
            ffma2(acc[q][3], hv.x, wa23.y);
            ffma2(acc[q][0], hv.y, wb01.x);
            ffma2(acc[q][1], hv.y, wb01.y);
            ffma2(acc[q][2], hv.y, wb23.x);
            ffma2(acc[q][3], hv.y, wb23.y);
        }
    }

    float4 bb;
    bb.x = bih[j0]   + bhh[j0];
    bb.y = bih[j0+1] + bhh[j0+1];
    bb.z = bih[j0+2] + bhh[j0+2];
    bb.w = bih[j0+3] + bhh[j0+3];
    #pragma unroll
    for (int q = 0; q < 8; q++) {
        int n = nbase + ng*8 + q;
        float2 u0 = unpk(acc[q][0]), u1 = unpk(acc[q][1]);
        float2 u2 = unpk(acc[q][2]), u3 = unpk(acc[q][3]);
        int dest = (ntime[n]*G_GRAPHS + batch[n])*C1 + j0;
        *(float4*)&g_xgates[dest] = make_float4(u0.x+u0.y+bb.x, u1.x+u1.y+bb.y,
                                                u2.x+u2.y+bb.z, u3.x+u3.y+bb.w);
    }
}

// LSTM: 1 graph/block (512 blocks), Whh row in regs, xgates prefetch, fused FC.
__global__ void __launch_bounds__(256) k_lstm(
        const float* __restrict__ Whh, const float* __restrict__ Wfc,
        const float* __restrict__ bfc, float* __restrict__ out) {
    __shared__ float hhs[64];
    __shared__ float gates[C1];
    int t = threadIdx.x;
    int g = blockIdx.x;

    unsigned long long w2[32];
    const float4* wrow = (const float4*)(Whh + t*64);
    #pragma unroll
    for (int i = 0; i < 16; i++) {
        float4 w = wrow[i];
        w2[2*i]   = pk(w.x, w.y);
        w2[2*i+1] = pk(w.z, w.w);
    }
    if (t < 64) hhs[t] = 0.f;
    float c = 0.f;
    float xg_cur = g_xgates[g*C1 + t];
    __syncthreads();

    for (int step = 0; step < T_STEPS; step++) {
        float xg_next = 0.f;
        if (step + 1 < T_STEPS) xg_next = g_xgates[((step+1)*G_GRAPHS + g)*C1 + t];
        unsigned long long aA = 0ull, aB = 0ull;
        #pragma unroll
        for (int k2 = 0; k2 < 16; k2++) {
            ulonglong2 hv = *(const ulonglong2*)&hhs[k2*4];
            ffma2(aA, hv.x, w2[2*k2]);
            ffma2(aB, hv.y, w2[2*k2+1]);
        }
        float2 a = unpk(aA), b = unpk(aB);
        gates[t] = xg_cur + a.x + a.y + b.x + b.y;
        __syncthreads();
        if (t < 64) {
            float ig = gates[t],       fg = gates[64 + t];
            float gg = gates[128 + t], og = gates[192 + t];
            c = sigf(fg)*c + sigf(ig)*tanhf(gg);
            hhs[t] = sigf(og)*tanhf(c);
        }
        __syncthreads();
        xg_cur = xg_next;
    }
    if (t < OUT_DIM) {
        float acc = bfc[t];
        #pragma unroll 8
        for (int k = 0; k < 64; k++) acc += hhs[k] * Wfc[k*OUT_DIM + t];
        out[g*OUT_DIM + t] = acc;
    }
}

// ---------------- launch ----------------
static const int SMEM_P2 = (16384 + P2N*260 + P2N*32) * 4;   // ~92 KB
static const int SMEM_XG = (16384 + XGN*68) * 4;             // ~74.2 KB

extern "C" void kernel_launch(void* const* d_in, const int* in_sizes, int n_in,
                              void* d_out, int out_size) {
    const float* x    = (const float*)d_in[0];
    const int*   ei   = (const int*)  d_in[1];
    const int*   batch= (const int*)  d_in[2];
    const int*   ntime= (const int*)  d_in[3];
    const float* W1   = (const float*)d_in[4];
    const float* as1  = (const float*)d_in[5];
    const float* ad1  = (const float*)d_in[6];
    const float* b1   = (const float*)d_in[7];
    const float* g1   = (const float*)d_in[8];
    const float* be1  = (const float*)d_in[9];
    const float* W2   = (const float*)d_in[10];
    const float* as2  = (const float*)d_in[11];
    const float* ad2  = (const float*)d_in[12];
    const float* b2   = (const float*)d_in[13];
    const float* g2   = (const float*)d_in[14];
    const float* be2  = (const float*)d_in[15];
    const float* Wih  = (const float*)d_in[16];
    const float* Whh  = (const float*)d_in[17];
    const float* bih  = (const float*)d_in[18];
    const float* bhh  = (const float*)d_in[19];
    const float* Wfc  = (const float*)d_in[20];
    const float* bfc  = (const float*)d_in[21];
    float* out = (float*)d_out;

    cudaFuncSetAttribute(k_proj2f,  cudaFuncAttributeMaxDynamicSharedMemorySize, SMEM_P2);
    cudaFuncSetAttribute(k_xgates2, cudaFuncAttributeMaxDynamicSharedMemorySize, SMEM_XG);

    void *p_xagg, *p_acc2, *p_den2;
    cudaGetSymbolAddress(&p_xagg, g_xagg);
    cudaGetSymbolAddress(&p_acc2, g_accum2);
    cudaGetSymbolAddress(&p_den2, g_denom2);
    cudaMemsetAsync(p_xagg, 0, sizeof(float)*N_NODES*32);
    cudaMemsetAsync(p_acc2, 0, sizeof(float)*N_NODES*HID);
    cudaMemsetAsync(p_den2, 0, sizeof(float)*N_NODES);

    k_pre1   <<<1, 64>>>(W1, as1, ad1);
    k_att1   <<<(N_NODES + 255)/256, 256>>>(x);
    k_esum1  <<<(ETOT + 255)/256, 256>>>(ei);
    k_proj2f <<<N_NODES/P2N, 256, SMEM_P2>>>(W1, b1, g1, be1, W2, as2, ad2);
    k_esum2  <<<(ETOT*8 + 255)/256, 256>>>(ei);
    k_xgates2<<<N_NODES/XGN, 256, SMEM_XG>>>(Wih, bih, bhh, b2, g2, be2, batch, ntime);
    k_lstm   <<<G_GRAPHS, 256>>>(Whh, Wfc, bfc, out);
}